// round 2
// baseline (speedup 1.0000x reference)
#include <cuda_runtime.h>

// T=4, B=2, L=2048, D=4096  -> per-timestep slice N = 2*2048*4096 = 16,777,216 floats
#define SLICE_N   (2 * 2048 * 4096)
#define SLICE_N4  (SLICE_N / 4)   // 4,194,304 float4 per slice

__device__ __forceinline__ float silu1(float v) {
    return v / (1.0f + __expf(-v));
}

__device__ __forceinline__ float4 silu4(float4 v) {
    float4 r;
    r.x = silu1(v.x);
    r.y = silu1(v.y);
    r.z = silu1(v.z);
    r.w = silu1(v.w);
    return r;
}

__device__ __forceinline__ float4 add4(float4 a, float4 b) {
    return make_float4(a.x + b.x, a.y + b.y, a.z + b.z, a.w + b.w);
}

__device__ __forceinline__ float4 sub4(float4 a, float4 b) {
    return make_float4(a.x - b.x, a.y - b.y, a.z - b.z, a.w - b.w);
}

__global__ void __launch_bounds__(256)
actswl_kernel(const float4* __restrict__ x, float4* __restrict__ out) {
    const int stride = gridDim.x * 256;

    for (int i = blockIdx.x * 256 + threadIdx.x; i < SLICE_N4; i += stride) {
        // Front-batched, fully coalesced streaming loads (evict-first: zero reuse).
        const float4 a0 = __ldcs(&x[i]);
        const float4 a1 = __ldcs(&x[i + SLICE_N4]);
        const float4 a2 = __ldcs(&x[i + 2 * SLICE_N4]);
        const float4 a3 = __ldcs(&x[i + 3 * SLICE_N4]);

        // t = 0
        float4 X  = a0;
        float4 y0 = silu4(X);
        __stcs(&out[i], y0);

        // t = 1
        X = add4(X, a1);
        float4 y1 = silu4(X);
        __stcs(&out[i + SLICE_N4], sub4(y1, y0));

        // t = 2
        X = add4(X, a2);
        float4 y2 = silu4(X);
        __stcs(&out[i + 2 * SLICE_N4], sub4(y2, y1));

        // t = 3
        X = add4(X, a3);
        float4 y3 = silu4(X);
        __stcs(&out[i + 3 * SLICE_N4], sub4(y3, y2));
    }
}

extern "C" void kernel_launch(void* const* d_in, const int* in_sizes, int n_in,
                              void* d_out, int out_size) {
    const float4* x = (const float4*)d_in[0];
    float4* out = (float4*)d_out;

    // Persistent single-wave launch: 148 SMs x 6 resident blocks (40-reg cap, 256 thr).
    const int blocks = 148 * 6;  // 888
    actswl_kernel<<<blocks, 256>>>(x, out);
}

// round 3
// speedup vs baseline: 1.1570x; 1.1570x over previous
#include <cuda_runtime.h>

// T=4, B=2, L=2048, D=4096  -> per-timestep slice N = 2*2048*4096 = 16,777,216 floats
#define SLICE_N   (2 * 2048 * 4096)
#define SLICE_N4  (SLICE_N / 4)   // 4,194,304 float4 per slice

__device__ __forceinline__ float silu1(float v) {
    return v / (1.0f + __expf(-v));
}

__device__ __forceinline__ float4 silu4(float4 v) {
    float4 r;
    r.x = silu1(v.x);
    r.y = silu1(v.y);
    r.z = silu1(v.z);
    r.w = silu1(v.w);
    return r;
}

__device__ __forceinline__ float4 add4(float4 a, float4 b) {
    return make_float4(a.x + b.x, a.y + b.y, a.z + b.z, a.w + b.w);
}

__device__ __forceinline__ float4 sub4(float4 a, float4 b) {
    return make_float4(a.x - b.x, a.y - b.y, a.z - b.z, a.w - b.w);
}

// Exact-fit, one-shot kernel. Each thread handles TWO float4 columns
// (offset by 256 within the block's 512-wide chunk) across all 4 timesteps:
// 8 independent 16B loads front-batched -> MLP_eff ~ 8 per thread.
__global__ void __launch_bounds__(256)
actswl_kernel(const float4* __restrict__ x, float4* __restrict__ out) {
    const int i0 = blockIdx.x * 512 + threadIdx.x;
    const int i1 = i0 + 256;

    // Front-batch all 8 global loads (coalesced 128B per warp per slice).
    const float4 a00 = x[i0];
    const float4 a01 = x[i1];
    const float4 a10 = x[i0 + SLICE_N4];
    const float4 a11 = x[i1 + SLICE_N4];
    const float4 a20 = x[i0 + 2 * SLICE_N4];
    const float4 a21 = x[i1 + 2 * SLICE_N4];
    const float4 a30 = x[i0 + 3 * SLICE_N4];
    const float4 a31 = x[i1 + 3 * SLICE_N4];

    // ---- column 0 ----
    float4 X0  = a00;
    float4 y00 = silu4(X0);
    out[i0] = y00;

    // ---- column 1 ----
    float4 X1  = a01;
    float4 y01 = silu4(X1);
    out[i1] = y01;

    // t = 1
    X0 = add4(X0, a10);
    float4 y10 = silu4(X0);
    out[i0 + SLICE_N4] = sub4(y10, y00);

    X1 = add4(X1, a11);
    float4 y11 = silu4(X1);
    out[i1 + SLICE_N4] = sub4(y11, y01);

    // t = 2
    X0 = add4(X0, a20);
    float4 y20 = silu4(X0);
    out[i0 + 2 * SLICE_N4] = sub4(y20, y10);

    X1 = add4(X1, a21);
    float4 y21 = silu4(X1);
    out[i1 + 2 * SLICE_N4] = sub4(y21, y11);

    // t = 3
    X0 = add4(X0, a30);
    float4 y30 = silu4(X0);
    out[i0 + 3 * SLICE_N4] = sub4(y30, y20);

    X1 = add4(X1, a31);
    float4 y31 = silu4(X1);
    out[i1 + 3 * SLICE_N4] = sub4(y31, y21);
}

extern "C" void kernel_launch(void* const* d_in, const int* in_sizes, int n_in,
                              void* d_out, int out_size) {
    const float4* x = (const float4*)d_in[0];
    float4* out = (float4*)d_out;

    const int blocks = SLICE_N4 / 512;  // 8192 blocks, exact fit
    actswl_kernel<<<blocks, 256>>>(x, out);
}

// round 4
// speedup vs baseline: 1.1620x; 1.0043x over previous
#include <cuda_runtime.h>

// T=4, B=2, L=2048, D=4096  -> per-timestep slice N = 2*2048*4096 = 16,777,216 floats
#define SLICE_N   (2 * 2048 * 4096)
#define SLICE_N4  (SLICE_N / 4)   // 4,194,304 float4 per slice

__device__ __forceinline__ float silu1(float v) {
    return v / (1.0f + __expf(-v));
}

__device__ __forceinline__ float4 silu4(float4 v) {
    float4 r;
    r.x = silu1(v.x);
    r.y = silu1(v.y);
    r.z = silu1(v.z);
    r.w = silu1(v.w);
    return r;
}

__device__ __forceinline__ float4 add4(float4 a, float4 b) {
    return make_float4(a.x + b.x, a.y + b.y, a.z + b.z, a.w + b.w);
}

__device__ __forceinline__ float4 sub4(float4 a, float4 b) {
    return make_float4(a.x - b.x, a.y - b.y, a.z - b.z, a.w - b.w);
}

// R1 winner structure (exact-fit, one column per thread, 4 front-batched loads)
// + streaming cache hints: zero-reuse data should not occupy L2 retention.
__global__ void __launch_bounds__(256, 1)
actswl_kernel(const float4* __restrict__ x, float4* __restrict__ out) {
    const int i = blockIdx.x * 256 + threadIdx.x;

    // Front-batch all 4 global loads (evict-first; coalesced 128B/warp/slice).
    const float4 a0 = __ldcs(&x[i]);
    const float4 a1 = __ldcs(&x[i + SLICE_N4]);
    const float4 a2 = __ldcs(&x[i + 2 * SLICE_N4]);
    const float4 a3 = __ldcs(&x[i + 3 * SLICE_N4]);

    // t = 0
    float4 X  = a0;
    float4 y0 = silu4(X);
    __stcs(&out[i], y0);

    // t = 1
    X = add4(X, a1);
    float4 y1 = silu4(X);
    __stcs(&out[i + SLICE_N4], sub4(y1, y0));

    // t = 2
    X = add4(X, a2);
    float4 y2 = silu4(X);
    __stcs(&out[i + 2 * SLICE_N4], sub4(y2, y1));

    // t = 3
    X = add4(X, a3);
    float4 y3 = silu4(X);
    __stcs(&out[i + 3 * SLICE_N4], sub4(y3, y2));
}

extern "C" void kernel_launch(void* const* d_in, const int* in_sizes, int n_in,
                              void* d_out, int out_size) {
    const float4* x = (const float4*)d_in[0];
    float4* out = (float4*)d_out;

    const int blocks = SLICE_N4 / 256;  // 16384 blocks, exact fit
    actswl_kernel<<<blocks, 256>>>(x, out);
}

// round 5
// speedup vs baseline: 1.1687x; 1.0058x over previous
#include <cuda_runtime.h>

// T=4, B=2, L=2048, D=4096  -> per-timestep slice N = 2*2048*4096 = 16,777,216 floats
#define SLICE_N   (2 * 2048 * 4096)
#define SLICE_N4  (SLICE_N / 4)   // 4,194,304 float4 per slice

__device__ __forceinline__ float silu1(float v) {
    // x * sigmoid(x) = x / (1 + e^-x); fast exp + fast divide (MUFU.EX2 + MUFU.RCP)
    return __fdividef(v, 1.0f + __expf(-v));
}

__device__ __forceinline__ float4 silu4(float4 v) {
    float4 r;
    r.x = silu1(v.x);
    r.y = silu1(v.y);
    r.z = silu1(v.z);
    r.w = silu1(v.w);
    return r;
}

__device__ __forceinline__ float4 add4(float4 a, float4 b) {
    return make_float4(a.x + b.x, a.y + b.y, a.z + b.z, a.w + b.w);
}

__device__ __forceinline__ float4 sub4(float4 a, float4 b) {
    return make_float4(a.x - b.x, a.y - b.y, a.z - b.z, a.w - b.w);
}

// R1 winner structure: exact-fit grid, one float4 column per thread,
// all 4 loads front-batched. Stores batched AFTER all compute so the
// load->MUFU dependent chain and the STG bursts don't interleave.
__global__ void __launch_bounds__(256, 1)
actswl_kernel(const float4* __restrict__ x, float4* __restrict__ out) {
    const int i = blockIdx.x * 256 + threadIdx.x;

    // Front-batch all 4 global loads (coalesced 512B/warp/slice).
    const float4 a0 = x[i];
    const float4 a1 = x[i + SLICE_N4];
    const float4 a2 = x[i + 2 * SLICE_N4];
    const float4 a3 = x[i + 3 * SLICE_N4];

    // Running prefix + silu, all in registers.
    float4 X  = a0;
    const float4 y0 = silu4(X);
    X = add4(X, a1);
    const float4 y1 = silu4(X);
    X = add4(X, a2);
    const float4 y2 = silu4(X);
    X = add4(X, a3);
    const float4 y3 = silu4(X);

    // Batched stores (fire-and-forget, issued back-to-back).
    out[i]                = y0;
    out[i + SLICE_N4]     = sub4(y1, y0);
    out[i + 2 * SLICE_N4] = sub4(y2, y1);
    out[i + 3 * SLICE_N4] = sub4(y3, y2);
}

extern "C" void kernel_launch(void* const* d_in, const int* in_sizes, int n_in,
                              void* d_out, int out_size) {
    const float4* x = (const float4*)d_in[0];
    float4* out = (float4*)d_out;

    const int blocks = SLICE_N4 / 256;  // 16384 blocks, exact fit
    actswl_kernel<<<blocks, 256>>>(x, out);
}